// round 2
// baseline (speedup 1.0000x reference)
#include <cuda_runtime.h>

// Problem constants (fixed by the dataset)
#define T_TOK   16384
#define D_DIM   4096
#define E_EXP   64
#define BM      128            // tokens per block
#define BK      32             // k-chunk
#define BKP     34             // smem row stride (even, !=0 mod 4 -> conflict-free LDS.64)
#define NBLK    (T_TOK / BM)   // 128 blocks
#define NCHUNK  (D_DIM / BK)   // 128 k-chunks
#define NTHREADS 256

typedef unsigned long long u64;

// Deterministic cross-block scratch (no device allocation allowed)
__device__ float g_ssum[NBLK * E_EXP];
__device__ int   g_cnt [NBLK * E_EXP];

__device__ __forceinline__ void fma2(u64 &d, u64 a, u64 b) {
    // packed fp32 FMA: (d.lo,d.hi) += (a.lo*b.lo, a.hi*b.hi)
    asm("fma.rn.f32x2 %0, %1, %2, %0;" : "+l"(d) : "l"(a), "l"(b));
}

__global__ void __launch_bounds__(NTHREADS, 1)
gate_main(const float* __restrict__ inp, const float* __restrict__ W,
          const float* __restrict__ bias, float* __restrict__ out)
{
    // smem pool: GEMM tiles (As 128x34 + Bs 64x34 = 6528 f) overlaid by logits (128x65 = 8320 f)
    __shared__ float pool[BM * (E_EXP + 1)];
    __shared__ float s_m[BM];
    __shared__ float s_inv[BM];
    __shared__ float s_ps[NTHREADS];
    __shared__ float s_b[E_EXP];
    __shared__ int   s_cnt[E_EXP];

    float* As = pool;                 // [BM][BKP], row-major along K
    float* Bs = pool + BM * BKP;      // [E_EXP][BKP]

    const int tid = threadIdx.x;
    const int blk = blockIdx.x;
    const int tg  = tid >> 3;   // 0..31  -> tokens {tg + 32*i}, i=0..3
    const int eg  = tid & 7;    // 0..7   -> experts {eg + 8*j}, j=0..7

    if (tid < E_EXP) s_b[tid] = bias[tid];

    // 32 packed accumulators (pair dimension = K; logit = lo + hi at the end)
    u64 acc[4][8];
#pragma unroll
    for (int i = 0; i < 4; ++i)
#pragma unroll
        for (int j = 0; j < 8; ++j) acc[i][j] = 0ULL;  // (+0.f,+0.f)

    // register prefetch buffers: inp 1024 f4 / 256 thr = 4; W 512/256 = 2
    float4 pa[4], pw[2];

    // ---- prefetch chunk 0 ----
    {
        const float* ip = inp + (size_t)blk * BM * D_DIM;
        const float* wp = W;
#pragma unroll
        for (int p = 0; p < 4; ++p) {
            int idx = p * NTHREADS + tid;
            int row = idx >> 3, q = idx & 7;
            pa[p] = *(const float4*)(ip + (size_t)row * D_DIM + q * 4);
        }
#pragma unroll
        for (int p = 0; p < 2; ++p) {
            int idx = p * NTHREADS + tid;
            int row = idx >> 3, q = idx & 7;
            pw[p] = *(const float4*)(wp + (size_t)row * D_DIM + q * 4);
        }
    }

    for (int c = 0; c < NCHUNK; ++c) {
        __syncthreads();   // previous inner-loop readers done
        // stage registers -> smem (float2 stores: BKP even keeps 8B alignment)
#pragma unroll
        for (int p = 0; p < 4; ++p) {
            int idx = p * NTHREADS + tid;
            int row = idx >> 3, q = idx & 7;
            float* d = &As[row * BKP + q * 4];
            *(float2*)(d)     = make_float2(pa[p].x, pa[p].y);
            *(float2*)(d + 2) = make_float2(pa[p].z, pa[p].w);
        }
#pragma unroll
        for (int p = 0; p < 2; ++p) {
            int idx = p * NTHREADS + tid;
            int row = idx >> 3, q = idx & 7;
            float* d = &Bs[row * BKP + q * 4];
            *(float2*)(d)     = make_float2(pw[p].x, pw[p].y);
            *(float2*)(d + 2) = make_float2(pw[p].z, pw[p].w);
        }
        __syncthreads();

        // prefetch next chunk while computing this one
        if (c + 1 < NCHUNK) {
            const float* ip = inp + (size_t)blk * BM * D_DIM + (size_t)(c + 1) * BK;
            const float* wp = W + (size_t)(c + 1) * BK;
#pragma unroll
            for (int p = 0; p < 4; ++p) {
                int idx = p * NTHREADS + tid;
                int row = idx >> 3, q = idx & 7;
                pa[p] = *(const float4*)(ip + (size_t)row * D_DIM + q * 4);
            }
#pragma unroll
            for (int p = 0; p < 2; ++p) {
                int idx = p * NTHREADS + tid;
                int row = idx >> 3, q = idx & 7;
                pw[p] = *(const float4*)(wp + (size_t)row * D_DIM + q * 4);
            }
        }

        // inner: 16 packed-K steps, 32 FMA2 each
#pragma unroll 4
        for (int kk2 = 0; kk2 < BK / 2; ++kk2) {
            u64 ta[4], wb[8];
#pragma unroll
            for (int i = 0; i < 4; ++i)
                ta[i] = *(const u64*)&As[(tg + 32 * i) * BKP + 2 * kk2];
#pragma unroll
            for (int j = 0; j < 8; ++j)
                wb[j] = *(const u64*)&Bs[(eg + 8 * j) * BKP + 2 * kk2];
#pragma unroll
            for (int i = 0; i < 4; ++i)
#pragma unroll
                for (int j = 0; j < 8; ++j)
                    fma2(acc[i][j], ta[i], wb[j]);
        }
    }

    // ---- epilogue: logits to smem (overlays As/Bs) ----
    __syncthreads();
    float* Ls = pool;   // [BM][65]
#pragma unroll
    for (int i = 0; i < 4; ++i) {
        int t = tg + 32 * i;
#pragma unroll
        for (int j = 0; j < 8; ++j) {
            int e = eg + 8 * j;
            float lo = __uint_as_float((unsigned)(acc[i][j] & 0xffffffffULL));
            float hi = __uint_as_float((unsigned)(acc[i][j] >> 32));
            Ls[t * (E_EXP + 1) + e] = lo + hi + s_b[e];
        }
    }
    if (tid < E_EXP) s_cnt[tid] = 0;
    __syncthreads();

    // per-token softmax / argmax (threads 0..127)
    if (tid < BM) {
        const float* lr = &Ls[tid * (E_EXP + 1)];
        float m = lr[0]; int am = 0;
#pragma unroll
        for (int e = 1; e < E_EXP; ++e) {
            float v = lr[e];
            if (v > m) { m = v; am = e; }
        }
        float den = 0.f;
#pragma unroll
        for (int e = 0; e < E_EXP; ++e) den += expf(lr[e] - m);
        float inv = 1.f / den;
        s_m[tid] = m; s_inv[tid] = inv;
        atomicAdd(&s_cnt[am], 1);                 // int atomic: deterministic
        int gt = blk * BM + tid;
        out[gt]          = (float)am;             // pruned_idx (cap 39322 > T: never pruned)
        out[T_TOK + gt]  = inv;                   // top1 score = exp(0)/den
    }
    __syncthreads();

    // per-expert score partial sums (deterministic fixed order)
    {
        int e = tid & 63, h = tid >> 6;           // 4 quarters of 32 tokens
        float s = 0.f;
        for (int t = h * 32; t < h * 32 + 32; ++t)
            s += expf(Ls[t * (E_EXP + 1) + e] - s_m[t]) * s_inv[t];
        s_ps[tid] = s;
    }
    __syncthreads();
    if (tid < E_EXP) {
        g_ssum[blk * E_EXP + tid] = s_ps[tid] + s_ps[64 + tid] + s_ps[128 + tid] + s_ps[192 + tid];
        g_cnt [blk * E_EXP + tid] = s_cnt[tid];
    }
}

__global__ void loss_kernel(float* __restrict__ out)
{
    __shared__ float red[E_EXP];
    int e = threadIdx.x;
    float ss = 0.f; int c = 0;
    for (int b = 0; b < NBLK; ++b) {              // fixed order: deterministic
        ss += g_ssum[b * E_EXP + e];
        c  += g_cnt [b * E_EXP + e];
    }
    red[e] = ss * (float)c;
    __syncthreads();
    for (int s = 32; s > 0; s >>= 1) {
        if (e < s) red[e] += red[e + s];
        __syncthreads();
    }
    if (e == 0)
        out[2 * T_TOK] = red[0] * (float)E_EXP / ((float)T_TOK * (float)T_TOK);
}

extern "C" void kernel_launch(void* const* d_in, const int* in_sizes, int n_in,
                              void* d_out, int out_size)
{
    const float* inp  = (const float*)d_in[0];
    const float* W    = (const float*)d_in[1];
    const float* bias = (const float*)d_in[2];
    float* out = (float*)d_out;   // layout: [0,T) idx as float, [T,2T) top1 score, [2T] loss

    gate_main<<<NBLK, NTHREADS>>>(inp, W, bias, out);
    loss_kernel<<<1, E_EXP>>>(out);
}

// round 4
// speedup vs baseline: 1.0795x; 1.0795x over previous
#include <cuda_runtime.h>
#include <cstdint>

// Problem constants (fixed by the dataset)
#define T_TOK   16384
#define D_DIM   4096
#define E_EXP   64
#define BM      128            // tokens per block
#define BK      32             // fp32 k per chunk (4 k8 steps)
#define NCHUNK  (D_DIM / BK)   // 128
#define NBLK    (T_TOK / BM)   // 128
#define NT      256

// per-stage permuted-fragment tiles (fp32): A 128x32 = 16KB, B 64x32 = 8KB
#define A_BYTES   16384
#define B_OFF     16384
#define STAGE_SZ  24576
#define SMEM_BYTES (2 * STAGE_SZ)   // 48KB; epilogue logits [128][65] overlay (33.3KB)

static __device__ float g_ssum[NBLK * E_EXP];
static __device__ int   g_cnt [NBLK * E_EXP];

// ---------- helpers ----------
__device__ __forceinline__ uint32_t smem_u32(const void* p) {
    uint32_t a;
    asm("{ .reg .u64 t; cvta.to.shared.u64 t, %1; cvt.u32.u64 %0, t; }" : "=r"(a) : "l"(p));
    return a;
}
__device__ __forceinline__ uint32_t tf32r(float x) {    // round-to-nearest tf32
    uint32_t r; asm("cvt.rna.tf32.f32 %0, %1;" : "=r"(r) : "f"(x)); return r;
}
__device__ __forceinline__ float4 lds128f(uint32_t a) {
    float4 v;
    asm volatile("ld.shared.v4.f32 {%0,%1,%2,%3}, [%4];"
                 : "=f"(v.x), "=f"(v.y), "=f"(v.z), "=f"(v.w) : "r"(a));
    return v;
}
__device__ __forceinline__ float2 lds64f(uint32_t a) {
    float2 v;
    asm volatile("ld.shared.v2.f32 {%0,%1}, [%2];" : "=f"(v.x), "=f"(v.y) : "r"(a));
    return v;
}
__device__ __forceinline__ void sts32f(uint32_t a, float v) {
    asm volatile("st.shared.f32 [%0], %1;" :: "r"(a), "f"(v));
}
__device__ __forceinline__ void mma_tf32(float* d, const uint32_t* a, const uint32_t* b) {
    asm volatile(
        "mma.sync.aligned.m16n8k8.row.col.f32.tf32.tf32.f32 "
        "{%0,%1,%2,%3}, {%4,%5,%6,%7}, {%8,%9}, {%0,%1,%2,%3};"
        : "+f"(d[0]), "+f"(d[1]), "+f"(d[2]), "+f"(d[3])
        : "r"(a[0]), "r"(a[1]), "r"(a[2]), "r"(a[3]), "r"(b[0]), "r"(b[1]));
}

// ---------- main fused kernel ----------
__global__ void __launch_bounds__(NT, 1)
gate_main(const float* __restrict__ inp, const float* __restrict__ W,
          const float* __restrict__ bias, float* __restrict__ out)
{
    extern __shared__ char dsm[];
    __shared__ float s_inv[BM];
    __shared__ float s_ps[NT];
    __shared__ float s_b[E_EXP];
    __shared__ int   s_cnt[E_EXP];

    const uint32_t sb = smem_u32(dsm);
    const int tid = threadIdx.x;
    const int blk = blockIdx.x;
    const int w   = tid >> 5;
    const int l   = tid & 31;
    const int tg  = w >> 1;       // token group: tokens [tg*32, tg*32+32)
    const int eg  = w & 1;        // expert group: experts [eg*32, eg*32+32)

    if (tid < E_EXP) { s_b[tid] = bias[tid]; s_cnt[tid] = 0; }

    // ---- staging pointers + permuted STS base addresses (chunk-invariant) ----
    // A: 128 rows x 8 float4 -> 4 per thread;  B: 64 x 8 -> 2 per thread
    const float4* pA[4]; uint32_t stA[4];
#pragma unroll
    for (int p = 0; p < 4; ++p) {
        int idx = p * NT + tid, row = idx >> 3, q = idx & 7;
        pA[p] = (const float4*)(inp + (size_t)(blk * BM + row) * D_DIM) + q;
        int mt = row >> 4, rr = row & 15, ks = q >> 1;
        int slot = (rr >> 3) + 2 * (q & 1);
        int lane0 = (rr & 7) * 4;
        stA[p] = (uint32_t)((((mt * 4 + ks) * 32 + lane0) * 4 + slot) * 4);
    }
    const float4* pW[2]; uint32_t stW[2];
#pragma unroll
    for (int p = 0; p < 2; ++p) {
        int idx = p * NT + tid, n = idx >> 3, q = idx & 7;
        pW[p] = (const float4*)(W + (size_t)n * D_DIM) + q;
        int nt = n >> 3, ks = q >> 1, slot = q & 1;
        int lane0 = (n & 7) * 4;
        stW[p] = (uint32_t)(B_OFF + (((nt * 4 + ks) * 32 + lane0) * 2 + slot) * 4);
    }

    // compute-side fragment LDS base addresses
    uint32_t ldA[2], ldB[4];
#pragma unroll
    for (int i = 0; i < 2; ++i)
        ldA[i] = (uint32_t)((((tg * 2 + i) * 4) * 32 + l) * 16);
#pragma unroll
    for (int j = 0; j < 4; ++j)
        ldB[j] = (uint32_t)(B_OFF + ((((eg * 4 + j) * 4) * 32 + l) * 8));

    float acc[2][4][4];
#pragma unroll
    for (int i = 0; i < 2; ++i)
#pragma unroll
        for (int j = 0; j < 4; ++j)
#pragma unroll
            for (int r = 0; r < 4; ++r) acc[i][j][r] = 0.f;

    float4 ra[4], rw[2];
#pragma unroll
    for (int p = 0; p < 4; ++p) ra[p] = pA[p][0];
#pragma unroll
    for (int p = 0; p < 2; ++p) rw[p] = pW[p][0];

    for (int c = 0; c < NCHUNK; ++c) {
        const uint32_t tb = sb + (c & 1) * STAGE_SZ;
        // store fp32, permuted into fragment order (4 scalar STS per float4)
#pragma unroll
        for (int p = 0; p < 4; ++p) {
            uint32_t a = tb + stA[p];
            sts32f(a, ra[p].x); sts32f(a + 16, ra[p].y);
            sts32f(a + 32, ra[p].z); sts32f(a + 48, ra[p].w);
        }
#pragma unroll
        for (int p = 0; p < 2; ++p) {
            uint32_t a = tb + stW[p];
            sts32f(a, rw[p].x); sts32f(a + 8, rw[p].y);
            sts32f(a + 16, rw[p].z); sts32f(a + 24, rw[p].w);
        }
        __syncthreads();   // single sync per chunk: see ordering argument (safe w/ dbl buffer)

        if (c + 1 < NCHUNK) {
#pragma unroll
            for (int p = 0; p < 4; ++p) ra[p] = pA[p][(c + 1) * (BK / 4)];
#pragma unroll
            for (int p = 0; p < 2; ++p) rw[p] = pW[p][(c + 1) * (BK / 4)];
        }

#pragma unroll
        for (int ks = 0; ks < 4; ++ks) {
            uint32_t ah[2][4], al[2][4], bh[4][2], bl[4][2];
#pragma unroll
            for (int i = 0; i < 2; ++i) {
                float4 af = lds128f(tb + ldA[i] + ks * 512);
                ah[i][0] = tf32r(af.x); al[i][0] = __float_as_uint(af.x - __uint_as_float(ah[i][0]));
                ah[i][1] = tf32r(af.y); al[i][1] = __float_as_uint(af.y - __uint_as_float(ah[i][1]));
                ah[i][2] = tf32r(af.z); al[i][2] = __float_as_uint(af.z - __uint_as_float(ah[i][2]));
                ah[i][3] = tf32r(af.w); al[i][3] = __float_as_uint(af.w - __uint_as_float(ah[i][3]));
            }
#pragma unroll
            for (int j = 0; j < 4; ++j) {
                float2 bf = lds64f(tb + ldB[j] + ks * 256);
                bh[j][0] = tf32r(bf.x); bl[j][0] = __float_as_uint(bf.x - __uint_as_float(bh[j][0]));
                bh[j][1] = tf32r(bf.y); bl[j][1] = __float_as_uint(bf.y - __uint_as_float(bh[j][1]));
            }
#pragma unroll
            for (int i = 0; i < 2; ++i)
#pragma unroll
                for (int j = 0; j < 4; ++j) {
                    mma_tf32(acc[i][j], ah[i], bh[j]);   // hi*hi
                    mma_tf32(acc[i][j], ah[i], bl[j]);   // hi*lo
                    mma_tf32(acc[i][j], al[i], bh[j]);   // lo*hi
                }
        }
    }
    __syncthreads();   // all compute done before logits overlay the tile buffers

    // ---- epilogue: fragments -> smem logits [128][65] ----
    float* Ls = (float*)dsm;
#pragma unroll
    for (int i = 0; i < 2; ++i) {
        int t0 = tg * 32 + i * 16 + (l >> 2);
#pragma unroll
        for (int j = 0; j < 4; ++j) {
            int e0 = eg * 32 + j * 8 + (l & 3) * 2;
            Ls[t0 * 65 + e0]       = acc[i][j][0];
            Ls[t0 * 65 + e0 + 1]   = acc[i][j][1];
            Ls[(t0 + 8) * 65 + e0]     = acc[i][j][2];
            Ls[(t0 + 8) * 65 + e0 + 1] = acc[i][j][3];
        }
    }
    __syncthreads();

    // per-token softmax / argmax (threads 0..127), write exp() back for reuse
    if (tid < BM) {
        float* lr = &Ls[tid * 65];
        float m = -1e30f; int am = 0;
#pragma unroll
        for (int e = 0; e < E_EXP; ++e) {
            float v = lr[e] + s_b[e];
            lr[e] = v;
            if (v > m) { m = v; am = e; }
        }
        float den = 0.f;
#pragma unroll
        for (int e = 0; e < E_EXP; ++e) {
            float p = expf(lr[e] - m);
            lr[e] = p;
            den += p;
        }
        float inv = 1.f / den;
        s_inv[tid] = inv;
        atomicAdd(&s_cnt[am], 1);          // int atomic: value-deterministic
        int gt = blk * BM + tid;
        out[gt]         = (float)am;       // pruned_idx (capacity 39322 > T: never pruned)
        out[T_TOK + gt] = inv;             // top1 score = exp(0)/den
    }
    __syncthreads();

    // per-expert score partial sums, fixed deterministic order
    {
        int e = tid & 63, h = tid >> 6;
        float s = 0.f;
#pragma unroll
        for (int i = 0; i < 32; ++i) {
            int t = h * 32 + i;
            s += Ls[t * 65 + e] * s_inv[t];
        }
        s_ps[tid] = s;
    }
    __syncthreads();
    if (tid < E_EXP) {
        g_ssum[blk * E_EXP + tid] = s_ps[tid] + s_ps[64 + tid] + s_ps[128 + tid] + s_ps[192 + tid];
        g_cnt [blk * E_EXP + tid] = s_cnt[tid];
    }
}

// ---------- loss reduction (deterministic fixed-order, 1024 threads) ----------
__global__ void loss_kernel(float* __restrict__ out)
{
    __shared__ float rs[1024];
    __shared__ int   rc[1024];
    int tid = threadIdx.x, e = tid & 63, h = tid >> 6;   // 16 groups of 8 blocks
    float ss = 0.f; int c = 0;
#pragma unroll
    for (int b = h * 8; b < h * 8 + 8; ++b) {
        ss += g_ssum[b * E_EXP + e];
        c  += g_cnt [b * E_EXP + e];
    }
    rs[tid] = ss; rc[tid] = c;
    __syncthreads();
    if (tid < E_EXP) {
        float S = 0.f; int C = 0;
#pragma unroll
        for (int g = 0; g < 16; ++g) { S += rs[g * 64 + e]; C += rc[g * 64 + e]; }
        rs[tid] = S * (float)C;
    }
    __syncthreads();
    for (int s = 32; s > 0; s >>= 1) {
        if (tid < s) rs[tid] += rs[tid + s];
        __syncthreads();
    }
    if (tid == 0)
        out[2 * T_TOK] = rs[0] * (float)E_EXP / ((float)T_TOK * (float)T_TOK);
}

extern "C" void kernel_launch(void* const* d_in, const int* in_sizes, int n_in,
                              void* d_out, int out_size)
{
    const float* inp  = (const float*)d_in[0];
    const float* W    = (const float*)d_in[1];
    const float* bias = (const float*)d_in[2];
    float* out = (float*)d_out;   // [0,T) idx, [T,2T) top1 score, [2T] loss

    cudaFuncSetAttribute(gate_main, cudaFuncAttributeMaxDynamicSharedMemorySize, SMEM_BYTES);
    gate_main<<<NBLK, NT, SMEM_BYTES>>>(inp, W, bias, out);
    loss_kernel<<<1, 1024>>>(out);
}

// round 5
// speedup vs baseline: 1.2729x; 1.1791x over previous
#include <cuda_runtime.h>
#include <cstdint>

// Problem constants (fixed by the dataset)
#define T_TOK   16384
#define D_DIM   4096
#define E_EXP   64
#define BM      128             // tokens per block
#define BK      32              // fp32 k per chunk (4 k8 steps)
#define NCHUNK  (D_DIM / BK)    // 128
#define NBLK    (T_TOK / BM)    // 128
#define NT      512

// row-major padded chunk tiles: stride 36 floats (bank = lane, conflict-free)
#define RS        36
#define A_BYTES   (BM * RS * 4)         // 18432
#define B_OFF     A_BYTES
#define STAGE_SZ  (A_BYTES + E_EXP * RS * 4)   // 27648
#define SMEM_BYTES (2 * STAGE_SZ)       // 55296 (epilogue Ls[128][65]=33280 fits)

static __device__ float g_ssum[NBLK * E_EXP];
static __device__ int   g_cnt [NBLK * E_EXP];
static __device__ int   g_arrived;   // zero-init; reset by last block each launch

// ---------- helpers ----------
__device__ __forceinline__ uint32_t smem_u32(const void* p) {
    uint32_t a;
    asm("{ .reg .u64 t; cvta.to.shared.u64 t, %1; cvt.u32.u64 %0, t; }" : "=r"(a) : "l"(p));
    return a;
}
__device__ __forceinline__ uint32_t tf32r(float x) {    // round-to-nearest tf32
    uint32_t r; asm("cvt.rna.tf32.f32 %0, %1;" : "=r"(r) : "f"(x)); return r;
}
__device__ __forceinline__ float ldsf(uint32_t a) {
    float v; asm volatile("ld.shared.f32 %0, [%1];" : "=f"(v) : "r"(a)); return v;
}
__device__ __forceinline__ void sts128(uint32_t a, float4 v) {
    asm volatile("st.shared.v4.f32 [%0], {%1,%2,%3,%4};"
                 :: "r"(a), "f"(v.x), "f"(v.y), "f"(v.z), "f"(v.w));
}
__device__ __forceinline__ void mma_tf32(float* d, const uint32_t* a, const uint32_t* b) {
    asm volatile(
        "mma.sync.aligned.m16n8k8.row.col.f32.tf32.tf32.f32 "
        "{%0,%1,%2,%3}, {%4,%5,%6,%7}, {%8,%9}, {%0,%1,%2,%3};"
        : "+f"(d[0]), "+f"(d[1]), "+f"(d[2]), "+f"(d[3])
        : "r"(a[0]), "r"(a[1]), "r"(a[2]), "r"(a[3]), "r"(b[0]), "r"(b[1]));
}

// ---------- single fused kernel ----------
__global__ void __launch_bounds__(NT, 1)
gate_main(const float* __restrict__ inp, const float* __restrict__ W,
          const float* __restrict__ bias, float* __restrict__ out)
{
    extern __shared__ char dsm[];
    __shared__ float s_inv[BM];
    __shared__ float s_ps[NT];
    __shared__ float s_b[E_EXP];
    __shared__ int   s_cnt[E_EXP];
    __shared__ int   s_last;
    __shared__ float rs2[NT];
    __shared__ int   rc2[NT];

    const uint32_t sb = smem_u32(dsm);
    const int tid = threadIdx.x;
    const int blk = blockIdx.x;
    const int w   = tid >> 5;
    const int l   = tid & 31;
    const int l4  = l >> 2;
    const int lk  = l & 3;
    const int tg  = w >> 2;       // 4 token groups of 32 tokens
    const int eg  = w & 3;        // 4 expert groups of 16 experts

    if (tid < E_EXP) { s_b[tid] = bias[tid]; s_cnt[tid] = 0; }

    // ---- staging (vectorized, conflict-free) ----
    // A: 1024 float4 per chunk / 512 thr = 2 ; W: 512 / 512 = 1
    const float4* pA[2]; uint32_t stA[2];
#pragma unroll
    for (int p = 0; p < 2; ++p) {
        int idx = p * NT + tid, row = idx >> 3, q = idx & 7;
        pA[p]  = (const float4*)(inp + (size_t)(blk * BM + row) * D_DIM) + q;
        stA[p] = (uint32_t)(row * (RS * 4) + q * 16);
    }
    const float4* pWp; uint32_t stW;
    {
        int row = tid >> 3, q = tid & 7;
        pWp = (const float4*)(W + (size_t)row * D_DIM) + q;
        stW = (uint32_t)(B_OFF + row * (RS * 4) + q * 16);
    }

    // compute-side scalar LDS bases (bank == lane: conflict-free)
    uint32_t aB[2], bB[2];
#pragma unroll
    for (int i = 0; i < 2; ++i)
        aB[i] = (uint32_t)(((tg * 32 + i * 16 + l4) * RS + lk) * 4);
#pragma unroll
    for (int j = 0; j < 2; ++j)
        bB[j] = (uint32_t)(B_OFF + ((eg * 16 + j * 8 + l4) * RS + lk) * 4);

    float acc[2][2][4];
#pragma unroll
    for (int i = 0; i < 2; ++i)
#pragma unroll
        for (int j = 0; j < 2; ++j)
#pragma unroll
            for (int r = 0; r < 4; ++r) acc[i][j][r] = 0.f;

    float4 ra[2], rw;
#pragma unroll
    for (int p = 0; p < 2; ++p) ra[p] = pA[p][0];
    rw = pWp[0];

    for (int c = 0; c < NCHUNK; ++c) {
        const uint32_t tb = sb + (c & 1) * STAGE_SZ;
        sts128(tb + stA[0], ra[0]);
        sts128(tb + stA[1], ra[1]);
        sts128(tb + stW,    rw);
        __syncthreads();   // dbl-buffer: reads of this buffer finished before prior sync

        if (c + 1 < NCHUNK) {
            ra[0] = pA[0][(c + 1) * (BK / 4)];
            ra[1] = pA[1][(c + 1) * (BK / 4)];
            rw    = pWp [(c + 1) * (BK / 4)];
        }

#pragma unroll
        for (int ks = 0; ks < 4; ++ks) {
            const uint32_t ko = ks * 32;   // 8 floats
            uint32_t ah[2][4], al[2][4], bh[2][2], bl[2][2];
#pragma unroll
            for (int i = 0; i < 2; ++i) {
                float a0 = ldsf(tb + aB[i] + ko);
                float a1 = ldsf(tb + aB[i] + ko + 8 * RS * 4);
                float a2 = ldsf(tb + aB[i] + ko + 16);
                float a3 = ldsf(tb + aB[i] + ko + 8 * RS * 4 + 16);
                ah[i][0] = tf32r(a0); al[i][0] = __float_as_uint(a0 - __uint_as_float(ah[i][0]));
                ah[i][1] = tf32r(a1); al[i][1] = __float_as_uint(a1 - __uint_as_float(ah[i][1]));
                ah[i][2] = tf32r(a2); al[i][2] = __float_as_uint(a2 - __uint_as_float(ah[i][2]));
                ah[i][3] = tf32r(a3); al[i][3] = __float_as_uint(a3 - __uint_as_float(ah[i][3]));
            }
#pragma unroll
            for (int j = 0; j < 2; ++j) {
                float b0 = ldsf(tb + bB[j] + ko);
                float b1 = ldsf(tb + bB[j] + ko + 16);
                bh[j][0] = tf32r(b0); bl[j][0] = __float_as_uint(b0 - __uint_as_float(bh[j][0]));
                bh[j][1] = tf32r(b1); bl[j][1] = __float_as_uint(b1 - __uint_as_float(bh[j][1]));
            }
            // 3 rounds of 4 independent MMAs (RAW distance 4, not 1)
            mma_tf32(acc[0][0], ah[0], bh[0]); mma_tf32(acc[0][1], ah[0], bh[1]);
            mma_tf32(acc[1][0], ah[1], bh[0]); mma_tf32(acc[1][1], ah[1], bh[1]);
            mma_tf32(acc[0][0], ah[0], bl[0]); mma_tf32(acc[0][1], ah[0], bl[1]);
            mma_tf32(acc[1][0], ah[1], bl[0]); mma_tf32(acc[1][1], ah[1], bl[1]);
            mma_tf32(acc[0][0], al[0], bh[0]); mma_tf32(acc[0][1], al[0], bh[1]);
            mma_tf32(acc[1][0], al[1], bh[0]); mma_tf32(acc[1][1], al[1], bh[1]);
        }
    }
    __syncthreads();   // last compute done before logits overlay tile buffers

    // ---- epilogue: fragments -> smem logits [128][65] ----
    float* Ls = (float*)dsm;
#pragma unroll
    for (int i = 0; i < 2; ++i) {
        int t0 = tg * 32 + i * 16 + l4;
#pragma unroll
        for (int j = 0; j < 2; ++j) {
            int e0 = eg * 16 + j * 8 + lk * 2;
            Ls[t0 * 65 + e0]           = acc[i][j][0];
            Ls[t0 * 65 + e0 + 1]       = acc[i][j][1];
            Ls[(t0 + 8) * 65 + e0]     = acc[i][j][2];
            Ls[(t0 + 8) * 65 + e0 + 1] = acc[i][j][3];
        }
    }
    __syncthreads();

    // per-token softmax / argmax (threads 0..127); store exp() back
    if (tid < BM) {
        float* lr = &Ls[tid * 65];
        float m = -1e30f; int am = 0;
#pragma unroll
        for (int e = 0; e < E_EXP; ++e) {
            float v = lr[e] + s_b[e];
            lr[e] = v;
            if (v > m) { m = v; am = e; }
        }
        float den = 0.f;
#pragma unroll
        for (int e = 0; e < E_EXP; ++e) {
            float p = expf(lr[e] - m);
            lr[e] = p;
            den += p;
        }
        float inv = 1.f / den;
        s_inv[tid] = inv;
        atomicAdd(&s_cnt[am], 1);          // int atomic: value-deterministic
        int gt = blk * BM + tid;
        out[gt]         = (float)am;       // pruned_idx (capacity 39322 > T: never pruned)
        out[T_TOK + gt] = inv;             // top1 score = exp(0)/den
    }
    __syncthreads();

    // per-expert score partial sums (fixed deterministic order; 512 thr, 8 slices)
    {
        int e = tid & 63, h = tid >> 6;
        float s = 0.f;
#pragma unroll
        for (int i = 0; i < 16; ++i) {
            int t = h * 16 + i;
            s += Ls[t * 65 + e] * s_inv[t];
        }
        s_ps[tid] = s;
    }
    __syncthreads();
    if (tid < E_EXP) {
        float S = 0.f;
#pragma unroll
        for (int g = 0; g < 8; ++g) S += s_ps[g * 64 + tid];
        g_ssum[blk * E_EXP + tid] = S;
        g_cnt [blk * E_EXP + tid] = s_cnt[tid];
    }
    __syncthreads();

    // ---- fused loss: last block reduces (deterministic fixed-order) ----
    if (tid == 0) {
        __threadfence();
        int n = atomicAdd(&g_arrived, 1);
        s_last = (n == NBLK - 1) ? 1 : 0;
    }
    __syncthreads();
    if (s_last) {
        __threadfence();
        int e = tid & 63, h = tid >> 6;      // 8 groups of 16 blocks
        float ss = 0.f; int c = 0;
#pragma unroll
        for (int b = h * 16; b < h * 16 + 16; ++b) {
            ss += g_ssum[b * E_EXP + e];
            c  += g_cnt [b * E_EXP + e];
        }
        rs2[tid] = ss; rc2[tid] = c;
        __syncthreads();
        if (tid < E_EXP) {
            float S = 0.f; int C = 0;
#pragma unroll
            for (int g = 0; g < 8; ++g) { S += rs2[g * 64 + tid]; C += rc2[g * 64 + tid]; }
            rs2[tid] = S * (float)C;
        }
        __syncthreads();
        if (tid == 0) {
            float tot = 0.f;
#pragma unroll
            for (int e2 = 0; e2 < E_EXP; ++e2) tot += rs2[e2];
            out[2 * T_TOK] = tot * (float)E_EXP / ((float)T_TOK * (float)T_TOK);
            g_arrived = 0;   // reset for next graph replay
        }
    }
}

extern "C" void kernel_launch(void* const* d_in, const int* in_sizes, int n_in,
                              void* d_out, int out_size)
{
    const float* inp  = (const float*)d_in[0];
    const float* W    = (const float*)d_in[1];
    const float* bias = (const float*)d_in[2];
    float* out = (float*)d_out;   // [0,T) idx, [T,2T) top1 score, [2T] loss

    cudaFuncSetAttribute(gate_main, cudaFuncAttributeMaxDynamicSharedMemorySize, SMEM_BYTES);
    gate_main<<<NBLK, NT, SMEM_BYTES>>>(inp, W, bias, out);
}